// round 4
// baseline (speedup 1.0000x reference)
#include <cuda_runtime.h>

// Shapes (fixed): B=1024, n=C*H*W=3072, c=10, m=9
#define NN 3072
#define CC 10
#define MM 9
#define BS 4                 // samples per block in the main kernel
#define MAX_B 8192

#define EPS2_INV 100.0f      // 1/EPSILON^2, EPSILON=0.1
#define NSTAB 1e-4f
#define SCALE 0.999f         // 1 - c*NUM_STAB

// Scratch (static device arrays — no allocation)
__device__ float g_Wt[CC * NN];     // W transposed: [c][n], float4-friendly
__device__ float g_M[CC * CC];      // W^T W
__device__ float g_reg[MAX_B];      // per-sample reg

// ---------------------------------------------------------------------------
// 1) Transpose W [n,c] -> Wt [c,n] (coalesced read of W)
__global__ void transpose_kernel(const float* __restrict__ W) {
    int idx = blockIdx.x * blockDim.x + threadIdx.x;
    if (idx < NN * CC) {
        int j = idx / CC, l = idx - j * CC;
        g_Wt[l * NN + j] = W[idx];
    }
}

// ---------------------------------------------------------------------------
// 2) M = W^T W  (100 blocks, one (l,l') entry each, vectorized over Wt rows)
__global__ void gram_kernel() {
    int pair = blockIdx.x;               // 0..99
    int l = pair / CC, lp = pair - l * CC;
    const float4* a = (const float4*)(g_Wt + l * NN);
    const float4* b = (const float4*)(g_Wt + lp * NN);
    float s = 0.f;
    for (int i = threadIdx.x; i < NN / 4; i += blockDim.x) {
        float4 av = a[i], bv = b[i];
        s += av.x * bv.x + av.y * bv.y + av.z * bv.z + av.w * bv.w;
    }
    #pragma unroll
    for (int o = 16; o; o >>= 1) s += __shfl_xor_sync(0xffffffffu, s, o);
    __shared__ float red[4];
    if ((threadIdx.x & 31) == 0) red[threadIdx.x >> 5] = s;
    __syncthreads();
    if (threadIdx.x == 0) g_M[pair] = red[0] + red[1] + red[2] + red[3];
}

// ---------------------------------------------------------------------------
// 3) Main: BS samples per block. GEMV z = Wt x + b (Wt float4 reused across
//    BS samples), then per-sample analytic-Jacobian epilogue on warps 0..BS-1.
__global__ __launch_bounds__(256) void isometry_kernel(
    const float* __restrict__ data, const float* __restrict__ bvec, int B) {
    const int b0 = blockIdx.x * BS;
    const int t = threadIdx.x;
    const int warp = t >> 5, lane = t & 31;

    // --- GEMV: acc[s][l], float4-vectorized, Wt shared across samples ---
    const float4* x4 = (const float4*)(data + (size_t)b0 * NN);
    const float4* w4 = (const float4*)g_Wt;

    float acc[BS][CC];
    #pragma unroll
    for (int s = 0; s < BS; s++)
        #pragma unroll
        for (int l = 0; l < CC; l++) acc[s][l] = 0.f;

    #pragma unroll
    for (int it = 0; it < (NN / 4) / 256; it++) {
        int j4 = t + it * 256;
        float4 xv[BS];
        #pragma unroll
        for (int s = 0; s < BS; s++) xv[s] = x4[s * (NN / 4) + j4];
        #pragma unroll
        for (int l = 0; l < CC; l++) {
            float4 wv = w4[l * (NN / 4) + j4];
            #pragma unroll
            for (int s = 0; s < BS; s++) {
                acc[s][l] = fmaf(xv[s].x, wv.x, acc[s][l]);
                acc[s][l] = fmaf(xv[s].y, wv.y, acc[s][l]);
                acc[s][l] = fmaf(xv[s].z, wv.z, acc[s][l]);
                acc[s][l] = fmaf(xv[s].w, wv.w, acc[s][l]);
            }
        }
    }
    // intra-warp reduce all BS*CC accumulators
    #pragma unroll
    for (int s = 0; s < BS; s++)
        #pragma unroll
        for (int l = 0; l < CC; l++) {
            float v = acc[s][l];
            #pragma unroll
            for (int o = 16; o; o >>= 1)
                v += __shfl_xor_sync(0xffffffffu, v, o);
            acc[s][l] = v;
        }

    __shared__ float red[8][BS][CC];
    if (lane == 0) {
        #pragma unroll
        for (int s = 0; s < BS; s++)
            #pragma unroll
            for (int l = 0; l < CC; l++) red[warp][s][l] = acc[s][l];
    }
    __syncthreads();
    if (warp >= BS) return;

    const int smp = warp;                 // one sample per warp
    if (b0 + smp >= B) return;

    // --- epilogue: z, softmax, analytic A, G = A M A^T, Frobenius norm ---
    __shared__ float z_sh[BS][CC];
    __shared__ float A_sh[BS][MM][CC];
    __shared__ float AM_sh[BS][MM][CC];

    if (lane < CC) {
        float zz = bvec[lane];
        #pragma unroll
        for (int w = 0; w < 8; w++) zz += red[w][smp][lane];
        z_sh[smp][lane] = zz;
    }
    __syncwarp();

    // every lane redundantly runs the scalar pipeline
    float z[CC];
    #pragma unroll
    for (int l = 0; l < CC; l++) z[l] = z_sh[smp][l];
    float mz = z[0];
    #pragma unroll
    for (int l = 1; l < CC; l++) mz = fmaxf(mz, z[l]);
    float e[CC], se = 0.f;
    #pragma unroll
    for (int l = 0; l < CC; l++) { e[l] = __expf(z[l] - mz); se += e[l]; }
    float inv = 1.f / se;
    float s_[CC], r[CC];
    #pragma unroll
    for (int l = 0; l < CC; l++) {
        s_[l] = e[l] * inv;
        r[l]  = sqrtf(fmaf(s_[l], SCALE, NSTAB));
    }
    float u = 1.f - r[MM];

    float sumr = 0.f;
    #pragma unroll
    for (int l = 0; l < CC; l++) sumr += r[l];
    float arg = fminf(fmaxf(sumr * 0.31622776601683794f, -1.f), 1.f);
    float delta  = 2.f * acosf(arg);
    float factor = delta * delta / (4.f * u * u) * EPS2_INV;

    if (lane < MM) {
        int k = lane;
        float g1 = SCALE * s_[k] / (r[k] * u);
        float g2 = SCALE * r[k] * s_[MM] / (r[MM] * u * u);
        float gs = g1 + g2;
        #pragma unroll
        for (int l = 0; l < CC; l++) {
            float A = -s_[l] * gs;
            if (l == k)  A += g1;
            if (l == MM) A += g2;
            A_sh[smp][k][l] = A;
        }
    }
    __syncwarp();
    if (lane < MM) {
        #pragma unroll
        for (int lp = 0; lp < CC; lp++) {
            float v = 0.f;
            #pragma unroll
            for (int l = 0; l < CC; l++)
                v = fmaf(A_sh[smp][lane][l], g_M[l * CC + lp], v);
            AM_sh[smp][lane][lp] = v;
        }
    }
    __syncwarp();

    // sum of squares of (G - factor*I): 81 entries over 32 lanes
    float ss = 0.f;
    for (int idx = lane; idx < MM * MM; idx += 32) {
        int i = idx / MM, j = idx - i * MM;
        float g = 0.f;
        #pragma unroll
        for (int l = 0; l < CC; l++)
            g = fmaf(AM_sh[smp][i][l], A_sh[smp][j][l], g);
        if (i == j) g -= factor;
        ss = fmaf(g, g, ss);
    }
    #pragma unroll
    for (int o = 16; o; o >>= 1) ss += __shfl_xor_sync(0xffffffffu, ss, o);
    if (lane == 0) g_reg[b0 + smp] = sqrtf(ss) * (1.0f / (float)NN);
}

// ---------------------------------------------------------------------------
// 4) Deterministic mean over B; out[1] = 0 (second tuple element)
__global__ void finalize_kernel(float* __restrict__ out, int out_size, int B) {
    __shared__ float red[8];
    int t = threadIdx.x;
    float s = 0.f;
    for (int i = t; i < B; i += 256) s += g_reg[i];
    #pragma unroll
    for (int o = 16; o; o >>= 1) s += __shfl_xor_sync(0xffffffffu, s, o);
    if ((t & 31) == 0) red[t >> 5] = s;
    __syncthreads();
    if (t == 0) {
        float tot = 0.f;
        #pragma unroll
        for (int w = 0; w < 8; w++) tot += red[w];
        out[0] = tot / (float)B;
    }
    for (int i = 1 + t; i < out_size; i += 256) out[i] = 0.0f;
}

// ---------------------------------------------------------------------------
extern "C" void kernel_launch(void* const* d_in, const int* in_sizes, int n_in,
                              void* d_out, int out_size) {
    const float* data = (const float*)d_in[0];   // [B, 3, 32, 32]
    const float* W    = (const float*)d_in[1];   // [3072, 10]
    const float* bvec = (const float*)d_in[2];   // [10]
    float* out = (float*)d_out;

    int B = in_sizes[0] / NN;
    if (B > MAX_B) B = MAX_B;

    transpose_kernel<<<(NN * CC + 255) / 256, 256>>>(W);
    gram_kernel<<<CC * CC, 128>>>();
    isometry_kernel<<<(B + BS - 1) / BS, 256>>>(data, bvec, B);
    finalize_kernel<<<1, 256>>>(out, out_size, B);
}